// round 9
// baseline (speedup 1.0000x reference)
#include <cuda_runtime.h>
#include <cstdint>

// STC_LIF recurrence, exact-fp32 sparse formulation.
// R9: consecutive-d lane mapping (lane l owns dims 4l..4l+3) -> x/out/m/bias
// become single 128-bit LSU ops per step (was 4x 32-bit), cutting MIO queue
// pressure that inflates on-chain LDS latency. Gather = R6's dynamic
// compaction (measured best): lanes rank spike bits via popc-prefix, scatter
// ascending k-indices to a per-warp buffer (double-buffered, one __syncwarp),
// pad with sentinel k=128 (zeros row) to a multiple of 4. Trailing +0.0 adds
// are exact no-ops; per-element FADD order identical to rel_err=0.0 kernels.

#define NSTEP 512
#define BATCH 1024
#define DIM 128
#define WARPS_PER_CTA 8
#define NCTAS (BATCH / WARPS_PER_CTA)        // 128
#define NTHREADS (WARPS_PER_CTA * 32)        // 256
#define W_KENT 129                            // k = 0..127 real, k = 128 zeros
#define SMEM_W_BYTES (W_KENT * 32 * 16)       // 66048
#define CBUF_U32 132                          // cnt(<=128) + 4 sentinels
#define SMEM_CBUF_BYTES (WARPS_PER_CTA * 2 * CBUF_U32 * 4)   // 8448
#define SMEM_BYTES (SMEM_W_BYTES + SMEM_CBUF_BYTES)

// XLA / Eigen fast tanh for f32 (matches jnp.tanh lowering; verified exact).
__device__ __forceinline__ float xla_tanh(float x) {
    float cx = fmaxf(fminf(x, 7.90531110763549805f), -7.90531110763549805f);
    float x2 = __fmul_rn(cx, cx);
    float p = __fmaf_rn(x2, -2.76076847742355e-16f, 2.00018790482477e-13f);
    p = __fmaf_rn(x2, p, -8.60467152213735e-11f);
    p = __fmaf_rn(x2, p, 5.12229709037114e-08f);
    p = __fmaf_rn(x2, p, 1.48572235717979e-05f);
    p = __fmaf_rn(x2, p, 6.37261928875436e-04f);
    p = __fmaf_rn(x2, p, 4.89352455891786e-03f);
    p = __fmul_rn(cx, p);
    float q = __fmaf_rn(x2, 1.19825839466702e-06f, 1.18534705686654e-04f);
    q = __fmaf_rn(x2, q, 2.26843463243900e-03f);
    q = __fmaf_rn(x2, q, 4.89352518554385e-03f);
    float t = __fdiv_rn(p, q);
    return (fabsf(x) < 0.0004f) ? x : t;
}

__global__ void __launch_bounds__(NTHREADS, 1)
stc_lif_kernel(const float* __restrict__ x,
               const float* __restrict__ mem0,
               const float* __restrict__ sp0,
               const float* __restrict__ W,      // [D, D], z[d] = sum_k s[k]*W[d,k]
               const float* __restrict__ bias,   // [D]
               float* __restrict__ out)
{
    // WTp[k*32 + l] is a float4 = { W[4l+0][k], W[4l+1][k], W[4l+2][k],
    // W[4l+3][k] }; entry k=128 is zeros (sentinel for padded slots).
    // Lane l's LDS.128 at entry k*32+l yields W[d,k] for its dims 4l..4l+3.
    extern __shared__ unsigned char smem_raw[];
    float4*   WTp  = (float4*)smem_raw;
    unsigned* cbuf = (unsigned*)(smem_raw + SMEM_W_BYTES);

    const int tid  = threadIdx.x;
    const int lane = tid & 31;
    const int warp = tid >> 5;
    const int row  = blockIdx.x * WARPS_PER_CTA + warp;   // 0..1023

    for (int e = tid; e < W_KENT * 32; e += NTHREADS) {
        int k = e >> 5, l = e & 31;
        float4 v;
        if (k < DIM) {
            v.x = W[(4 * l + 0) * DIM + k];
            v.y = W[(4 * l + 1) * DIM + k];
            v.z = W[(4 * l + 2) * DIM + k];
            v.w = W[(4 * l + 3) * DIM + k];
        } else {
            v = make_float4(0.0f, 0.0f, 0.0f, 0.0f);
        }
        WTp[e] = v;
    }
    __syncthreads();

    const int dbase = 4 * lane;                            // this lane's dims

    const float4 bv = *(const float4*)(bias + dbase);
    float4 m = *(const float4*)(mem0 + (size_t)row * DIM + dbase);

    // Spike flags for dims 4l..4l+3; ballot word c: bit l = flag of dim 4l+c.
    float4 sv = *(const float4*)(sp0 + (size_t)row * DIM + dbase);
    bool f0 = sv.x != 0.0f, f1 = sv.y != 0.0f, f2 = sv.z != 0.0f, f3 = sv.w != 0.0f;
    unsigned w0 = __ballot_sync(0xffffffffu, f0);
    unsigned w1 = __ballot_sync(0xffffffffu, f1);
    unsigned w2 = __ballot_sync(0xffffffffu, f2);
    unsigned w3 = __ballot_sync(0xffffffffu, f3);

    const size_t step_stride = (size_t)BATCH * DIM;       // 131072
    const float* xp    = x + (size_t)row * DIM + dbase;
    const float* xlast = xp + (size_t)(NSTEP - 1) * step_stride;
    float*       op    = out + (size_t)row * DIM + dbase;

    // 2-deep x prefetch.
    float4 xa = *(const float4*)xp;
    float4 xb = *(const float4*)(xp + step_stride);

    const unsigned mlt = (1u << lane) - 1u;               // lanemask_lt
    const char* Wlb = (const char*)(WTp + lane);          // +k*512 bytes per k
    unsigned* cb_base = cbuf + warp * 2 * CBUF_U32;

    for (int i = 0; i < NSTEP; i++) {
        const float* xq = xp + 2 * step_stride;
        if (xq > xlast) xq = xlast;
        float4 xc = *(const float4*)xq;

        // ---- compaction: rank(4l+c) = S + sum_{c'<c} bit_l(w_c') ----
        unsigned* cb = cb_base + (i & 1) * CBUF_U32;
        unsigned S = __popc(w0 & mlt) + __popc(w1 & mlt)
                   + __popc(w2 & mlt) + __popc(w3 & mlt);
        unsigned b0 = (w0 >> lane) & 1u;
        unsigned b1 = (w1 >> lane) & 1u;
        unsigned b2 = (w2 >> lane) & 1u;
        unsigned r0 = S;
        unsigned r1 = S + b0;
        unsigned r2 = r1 + b1;
        unsigned r3 = r2 + b2;
        unsigned cnt = __popc(w0) + __popc(w1) + __popc(w2) + __popc(w3);

        if (lane < 4) cb[cnt + lane] = 128u;              // sentinels -> zeros
        if (f0) cb[r0] = (unsigned)(dbase + 0);
        if (f1) cb[r1] = (unsigned)(dbase + 1);
        if (f2) cb[r2] = (unsigned)(dbase + 2);
        if (f3) cb[r3] = (unsigned)(dbase + 3);
        __syncwarp();

        // ---- z[d] = ascending-k sparse sum; pads add exact +0.0 ----
        float z0 = 0.0f, z1 = 0.0f, z2 = 0.0f, z3 = 0.0f;
        const uint4* cb4 = (const uint4*)cb;
        for (unsigned j = 0; j < cnt; j += 4) {
            uint4 id = cb4[j >> 2];                       // broadcast LDS.128
            float4 a = *(const float4*)(Wlb + id.x * 512);
            float4 b = *(const float4*)(Wlb + id.y * 512);
            float4 c = *(const float4*)(Wlb + id.z * 512);
            float4 d = *(const float4*)(Wlb + id.w * 512);
            z0 = __fadd_rn(z0, a.x); z1 = __fadd_rn(z1, a.y);
            z2 = __fadd_rn(z2, a.z); z3 = __fadd_rn(z3, a.w);
            z0 = __fadd_rn(z0, b.x); z1 = __fadd_rn(z1, b.y);
            z2 = __fadd_rn(z2, b.z); z3 = __fadd_rn(z3, b.w);
            z0 = __fadd_rn(z0, c.x); z1 = __fadd_rn(z1, c.y);
            z2 = __fadd_rn(z2, c.z); z3 = __fadd_rn(z3, c.w);
            z0 = __fadd_rn(z0, d.x); z1 = __fadd_rn(z1, d.y);
            z2 = __fadd_rn(z2, d.z); z3 = __fadd_rn(z3, d.w);
        }

        // gamma = (1 + tanh(z + b)) * 0.5   (unfused, XLA rounding)
        float t0 = xla_tanh(__fadd_rn(z0, bv.x));
        float t1 = xla_tanh(__fadd_rn(z1, bv.y));
        float t2 = xla_tanh(__fadd_rn(z2, bv.z));
        float t3 = xla_tanh(__fadd_rn(z3, bv.w));
        float g0 = __fmul_rn(__fadd_rn(1.0f, t0), 0.5f);
        float g1 = __fmul_rn(__fadd_rn(1.0f, t1), 0.5f);
        float g2 = __fmul_rn(__fadd_rn(1.0f, t2), 0.5f);
        float g3 = __fmul_rn(__fadd_rn(1.0f, t3), 0.5f);

        // m = m + x * gamma  (mul then add, unfused)
        m.x = __fadd_rn(m.x, __fmul_rn(xa.x, g0));
        m.y = __fadd_rn(m.y, __fmul_rn(xa.y, g1));
        m.z = __fadd_rn(m.z, __fmul_rn(xa.z, g2));
        m.w = __fadd_rn(m.w, __fmul_rn(xa.w, g3));

        // spike = (m >= 1); reset m to 0 on spike (== m*(1-s), exact)
        f0 = (m.x >= 1.0f); f1 = (m.y >= 1.0f); f2 = (m.z >= 1.0f); f3 = (m.w >= 1.0f);

        float4 s;
        s.x = f0 ? 1.0f : 0.0f;  s.y = f1 ? 1.0f : 0.0f;
        s.z = f2 ? 1.0f : 0.0f;  s.w = f3 ? 1.0f : 0.0f;
        *(float4*)op = s;                                 // one STG.128

        w0 = __ballot_sync(0xffffffffu, f0);
        w1 = __ballot_sync(0xffffffffu, f1);
        w2 = __ballot_sync(0xffffffffu, f2);
        w3 = __ballot_sync(0xffffffffu, f3);

        m.x = f0 ? 0.0f : m.x;  m.y = f1 ? 0.0f : m.y;
        m.z = f2 ? 0.0f : m.z;  m.w = f3 ? 0.0f : m.w;

        xa = xb; xb = xc;
        xp += step_stride;
        op += step_stride;
    }
}

extern "C" void kernel_launch(void* const* d_in, const int* in_sizes, int n_in,
                              void* d_out, int out_size)
{
    (void)in_sizes; (void)n_in; (void)out_size;
    const float* x    = (const float*)d_in[0];
    const float* mem0 = (const float*)d_in[1];
    const float* sp0  = (const float*)d_in[2];
    const float* Wgs  = (const float*)d_in[3];
    const float* bgs  = (const float*)d_in[4];
    // d_in[5], d_in[6] (W_gt_w, W_gt_b) are dead in the reference's 3D branch.
    float* out = (float*)d_out;

    (void)cudaFuncSetAttribute(stc_lif_kernel,
                               cudaFuncAttributeMaxDynamicSharedMemorySize,
                               SMEM_BYTES);
    stc_lif_kernel<<<NCTAS, NTHREADS, SMEM_BYTES>>>(x, mem0, sp0, Wgs, bgs, out);
}

// round 10
// speedup vs baseline: 1.5130x; 1.5130x over previous
#include <cuda_runtime.h>
#include <cstdint>

// STC_LIF recurrence, exact-fp32 sparse formulation.
// R10: R6's measured-best dynamic compaction gather + consecutive-d lane
// mapping (lane l owns dims 4l..4l+3 -> one LDG.128 + one STG.128 per step),
// with SIMPLE 1-ahead x prefetch. (R3/R9 showed the 2-deep clamped prefetch
// regresses ~150us; this isolates the vectorization change.)
// Compaction: lanes rank spike bits via popc-prefix, scatter ascending
// k-indices to a per-warp double-buffered buffer, pad with sentinel k=128
// (zeros row) to a multiple of 4; trailing +0.0 adds are exact no-ops, so the
// per-element FADD order is identical to the rel_err=0.0 kernels.

#define NSTEP 512
#define BATCH 1024
#define DIM 128
#define WARPS_PER_CTA 8
#define NCTAS (BATCH / WARPS_PER_CTA)        // 128
#define NTHREADS (WARPS_PER_CTA * 32)        // 256
#define W_KENT 129                            // k = 0..127 real, k = 128 zeros
#define SMEM_W_BYTES (W_KENT * 32 * 16)       // 66048
#define CBUF_U32 132                          // cnt(<=128) + 4 sentinels
#define SMEM_CBUF_BYTES (WARPS_PER_CTA * 2 * CBUF_U32 * 4)   // 8448
#define SMEM_BYTES (SMEM_W_BYTES + SMEM_CBUF_BYTES)

// XLA / Eigen fast tanh for f32 (matches jnp.tanh lowering; verified exact).
__device__ __forceinline__ float xla_tanh(float x) {
    float cx = fmaxf(fminf(x, 7.90531110763549805f), -7.90531110763549805f);
    float x2 = __fmul_rn(cx, cx);
    float p = __fmaf_rn(x2, -2.76076847742355e-16f, 2.00018790482477e-13f);
    p = __fmaf_rn(x2, p, -8.60467152213735e-11f);
    p = __fmaf_rn(x2, p, 5.12229709037114e-08f);
    p = __fmaf_rn(x2, p, 1.48572235717979e-05f);
    p = __fmaf_rn(x2, p, 6.37261928875436e-04f);
    p = __fmaf_rn(x2, p, 4.89352455891786e-03f);
    p = __fmul_rn(cx, p);
    float q = __fmaf_rn(x2, 1.19825839466702e-06f, 1.18534705686654e-04f);
    q = __fmaf_rn(x2, q, 2.26843463243900e-03f);
    q = __fmaf_rn(x2, q, 4.89352518554385e-03f);
    float t = __fdiv_rn(p, q);
    return (fabsf(x) < 0.0004f) ? x : t;
}

__global__ void __launch_bounds__(NTHREADS, 1)
stc_lif_kernel(const float* __restrict__ x,
               const float* __restrict__ mem0,
               const float* __restrict__ sp0,
               const float* __restrict__ W,      // [D, D], z[d] = sum_k s[k]*W[d,k]
               const float* __restrict__ bias,   // [D]
               float* __restrict__ out)
{
    // WTp[k*32 + l] is a float4 = { W[4l+0][k], W[4l+1][k], W[4l+2][k],
    // W[4l+3][k] }; entry k=128 is zeros (sentinel for padded slots).
    // Lane l's LDS.128 at entry k*32+l yields W[d,k] for its dims 4l..4l+3.
    extern __shared__ unsigned char smem_raw[];
    float4*   WTp  = (float4*)smem_raw;
    unsigned* cbuf = (unsigned*)(smem_raw + SMEM_W_BYTES);

    const int tid  = threadIdx.x;
    const int lane = tid & 31;
    const int warp = tid >> 5;
    const int row  = blockIdx.x * WARPS_PER_CTA + warp;   // 0..1023

    for (int e = tid; e < W_KENT * 32; e += NTHREADS) {
        int k = e >> 5, l = e & 31;
        float4 v;
        if (k < DIM) {
            v.x = W[(4 * l + 0) * DIM + k];
            v.y = W[(4 * l + 1) * DIM + k];
            v.z = W[(4 * l + 2) * DIM + k];
            v.w = W[(4 * l + 3) * DIM + k];
        } else {
            v = make_float4(0.0f, 0.0f, 0.0f, 0.0f);
        }
        WTp[e] = v;
    }
    __syncthreads();

    const int dbase = 4 * lane;                            // this lane's dims

    const float4 bv = *(const float4*)(bias + dbase);
    float4 m = *(const float4*)(mem0 + (size_t)row * DIM + dbase);

    // Spike flags for dims 4l..4l+3; ballot word c: bit l = flag of dim 4l+c.
    float4 sv = *(const float4*)(sp0 + (size_t)row * DIM + dbase);
    bool f0 = sv.x != 0.0f, f1 = sv.y != 0.0f, f2 = sv.z != 0.0f, f3 = sv.w != 0.0f;
    unsigned w0 = __ballot_sync(0xffffffffu, f0);
    unsigned w1 = __ballot_sync(0xffffffffu, f1);
    unsigned w2 = __ballot_sync(0xffffffffu, f2);
    unsigned w3 = __ballot_sync(0xffffffffu, f3);

    const size_t step_stride = (size_t)BATCH * DIM;       // 131072
    const float* xp = x   + (size_t)row * DIM + dbase;
    float*       op = out + (size_t)row * DIM + dbase;

    float4 xa = *(const float4*)xp;                       // step-0 prefetch

    const unsigned mlt = (1u << lane) - 1u;               // lanemask_lt
    const char* Wlb = (const char*)(WTp + lane);          // +k*512 bytes per k
    unsigned* cb_base = cbuf + warp * 2 * CBUF_U32;

    for (int i = 0; i < NSTEP; i++) {
        // Simple 1-ahead prefetch (last iter re-reads current; value unused).
        const float* xq = (i + 1 < NSTEP) ? (xp + step_stride) : xp;
        float4 xn = *(const float4*)xq;

        // ---- compaction: rank(4l+c) = S + sum_{c'<c} bit_l(w_c') ----
        unsigned* cb = cb_base + (i & 1) * CBUF_U32;
        unsigned S = __popc(w0 & mlt) + __popc(w1 & mlt)
                   + __popc(w2 & mlt) + __popc(w3 & mlt);
        unsigned b0 = (w0 >> lane) & 1u;
        unsigned b1 = (w1 >> lane) & 1u;
        unsigned b2 = (w2 >> lane) & 1u;
        unsigned r0 = S;
        unsigned r1 = S + b0;
        unsigned r2 = r1 + b1;
        unsigned r3 = r2 + b2;
        unsigned cnt = __popc(w0) + __popc(w1) + __popc(w2) + __popc(w3);

        if (lane < 4) cb[cnt + lane] = 128u;              // sentinels -> zeros
        if (f0) cb[r0] = (unsigned)(dbase + 0);
        if (f1) cb[r1] = (unsigned)(dbase + 1);
        if (f2) cb[r2] = (unsigned)(dbase + 2);
        if (f3) cb[r3] = (unsigned)(dbase + 3);
        __syncwarp();

        // ---- z[d] = ascending-k sparse sum; pads add exact +0.0 ----
        float z0 = 0.0f, z1 = 0.0f, z2 = 0.0f, z3 = 0.0f;
        const uint4* cb4 = (const uint4*)cb;
        for (unsigned j = 0; j < cnt; j += 4) {
            uint4 id = cb4[j >> 2];                       // broadcast LDS.128
            float4 a = *(const float4*)(Wlb + id.x * 512);
            float4 b = *(const float4*)(Wlb + id.y * 512);
            float4 c = *(const float4*)(Wlb + id.z * 512);
            float4 d = *(const float4*)(Wlb + id.w * 512);
            z0 = __fadd_rn(z0, a.x); z1 = __fadd_rn(z1, a.y);
            z2 = __fadd_rn(z2, a.z); z3 = __fadd_rn(z3, a.w);
            z0 = __fadd_rn(z0, b.x); z1 = __fadd_rn(z1, b.y);
            z2 = __fadd_rn(z2, b.z); z3 = __fadd_rn(z3, b.w);
            z0 = __fadd_rn(z0, c.x); z1 = __fadd_rn(z1, c.y);
            z2 = __fadd_rn(z2, c.z); z3 = __fadd_rn(z3, c.w);
            z0 = __fadd_rn(z0, d.x); z1 = __fadd_rn(z1, d.y);
            z2 = __fadd_rn(z2, d.z); z3 = __fadd_rn(z3, d.w);
        }

        // gamma = (1 + tanh(z + b)) * 0.5   (unfused, XLA rounding)
        float t0 = xla_tanh(__fadd_rn(z0, bv.x));
        float t1 = xla_tanh(__fadd_rn(z1, bv.y));
        float t2 = xla_tanh(__fadd_rn(z2, bv.z));
        float t3 = xla_tanh(__fadd_rn(z3, bv.w));
        float g0 = __fmul_rn(__fadd_rn(1.0f, t0), 0.5f);
        float g1 = __fmul_rn(__fadd_rn(1.0f, t1), 0.5f);
        float g2 = __fmul_rn(__fadd_rn(1.0f, t2), 0.5f);
        float g3 = __fmul_rn(__fadd_rn(1.0f, t3), 0.5f);

        // m = m + x * gamma  (mul then add, unfused)
        m.x = __fadd_rn(m.x, __fmul_rn(xa.x, g0));
        m.y = __fadd_rn(m.y, __fmul_rn(xa.y, g1));
        m.z = __fadd_rn(m.z, __fmul_rn(xa.z, g2));
        m.w = __fadd_rn(m.w, __fmul_rn(xa.w, g3));

        // spike = (m >= 1); reset m to 0 on spike (== m*(1-s), exact)
        f0 = (m.x >= 1.0f); f1 = (m.y >= 1.0f); f2 = (m.z >= 1.0f); f3 = (m.w >= 1.0f);

        float4 s;
        s.x = f0 ? 1.0f : 0.0f;  s.y = f1 ? 1.0f : 0.0f;
        s.z = f2 ? 1.0f : 0.0f;  s.w = f3 ? 1.0f : 0.0f;
        *(float4*)op = s;                                 // one STG.128

        w0 = __ballot_sync(0xffffffffu, f0);
        w1 = __ballot_sync(0xffffffffu, f1);
        w2 = __ballot_sync(0xffffffffu, f2);
        w3 = __ballot_sync(0xffffffffu, f3);

        m.x = f0 ? 0.0f : m.x;  m.y = f1 ? 0.0f : m.y;
        m.z = f2 ? 0.0f : m.z;  m.w = f3 ? 0.0f : m.w;

        xa = xn;
        xp += step_stride;
        op += step_stride;
    }
}

extern "C" void kernel_launch(void* const* d_in, const int* in_sizes, int n_in,
                              void* d_out, int out_size)
{
    (void)in_sizes; (void)n_in; (void)out_size;
    const float* x    = (const float*)d_in[0];
    const float* mem0 = (const float*)d_in[1];
    const float* sp0  = (const float*)d_in[2];
    const float* Wgs  = (const float*)d_in[3];
    const float* bgs  = (const float*)d_in[4];
    // d_in[5], d_in[6] (W_gt_w, W_gt_b) are dead in the reference's 3D branch.
    float* out = (float*)d_out;

    (void)cudaFuncSetAttribute(stc_lif_kernel,
                               cudaFuncAttributeMaxDynamicSharedMemorySize,
                               SMEM_BYTES);
    stc_lif_kernel<<<NCTAS, NTHREADS, SMEM_BYTES>>>(x, mem0, sp0, Wgs, bgs, out);
}

// round 12
// speedup vs baseline: 1.7663x; 1.1674x over previous
#include <cuda_runtime.h>
#include <cstdint>

// STC_LIF recurrence, exact-fp32 sparse formulation.
// R11/R12: load-balance fix — 7 rows/CTA x 147 CTAs (224 thr) so ~every one
// of the 148 SMs carries one CTA (max 7 warps/SM). R10's 128-CTA launch left
// 20 SMs idle while busy SMs carried 8 warps; this latency-bound kernel
// scales with max warps/SM -> ~12% win. Plus: ballots moved directly after
// the spike compare (shortens the recurrence chain), and an L2 prefetch hint
// for x at i+2 (no live registers -> avoids the R9 deep-prefetch regression).
// Gather = R6/R10 measured-best dynamic compaction; numerics byte-identical
// to the rel_err=0.0 kernels (ascending-k sum, bias last, XLA tanh).

#define NSTEP 512
#define BATCH 1024
#define DIM 128
#define ROWS_PER_CTA 7
#define NCTAS ((BATCH + ROWS_PER_CTA - 1) / ROWS_PER_CTA)   // 147
#define NTHREADS (ROWS_PER_CTA * 32)                         // 224
#define W_KENT 129                            // k = 0..127 real, k = 128 zeros
#define SMEM_W_BYTES (W_KENT * 32 * 16)       // 66048
#define CBUF_U32 132                          // cnt(<=128) + 4 sentinels
#define SMEM_CBUF_BYTES (ROWS_PER_CTA * 2 * CBUF_U32 * 4)    // 7392
#define SMEM_BYTES (SMEM_W_BYTES + SMEM_CBUF_BYTES)

// XLA / Eigen fast tanh for f32 (matches jnp.tanh lowering; verified exact).
__device__ __forceinline__ float xla_tanh(float x) {
    float cx = fmaxf(fminf(x, 7.90531110763549805f), -7.90531110763549805f);
    float x2 = __fmul_rn(cx, cx);
    float p = __fmaf_rn(x2, -2.76076847742355e-16f, 2.00018790482477e-13f);
    p = __fmaf_rn(x2, p, -8.60467152213735e-11f);
    p = __fmaf_rn(x2, p, 5.12229709037114e-08f);
    p = __fmaf_rn(x2, p, 1.48572235717979e-05f);
    p = __fmaf_rn(x2, p, 6.37261928875436e-04f);
    p = __fmaf_rn(x2, p, 4.89352455891786e-03f);
    p = __fmul_rn(cx, p);
    float q = __fmaf_rn(x2, 1.19825839466702e-06f, 1.18534705686654e-04f);
    q = __fmaf_rn(x2, q, 2.26843463243900e-03f);
    q = __fmaf_rn(x2, q, 4.89352518554385e-03f);
    float t = __fdiv_rn(p, q);
    return (fabsf(x) < 0.0004f) ? x : t;
}

__global__ void __launch_bounds__(NTHREADS, 1)
stc_lif_kernel(const float* __restrict__ x,
               const float* __restrict__ mem0,
               const float* __restrict__ sp0,
               const float* __restrict__ W,      // [D, D], z[d] = sum_k s[k]*W[d,k]
               const float* __restrict__ bias,   // [D]
               float* __restrict__ out)
{
    // WTp[k*32 + l] is a float4 = { W[4l+0][k], W[4l+1][k], W[4l+2][k],
    // W[4l+3][k] }; entry k=128 is zeros (sentinel for padded slots).
    // Lane l's LDS.128 at entry k*32+l yields W[d,k] for its dims 4l..4l+3.
    extern __shared__ unsigned char smem_raw[];
    float4*   WTp  = (float4*)smem_raw;
    unsigned* cbuf = (unsigned*)(smem_raw + SMEM_W_BYTES);

    const int tid  = threadIdx.x;
    const int lane = tid & 31;
    const int warp = tid >> 5;
    const int row  = blockIdx.x * ROWS_PER_CTA + warp;    // 0..1023 (+tail)

    for (int e = tid; e < W_KENT * 32; e += NTHREADS) {
        int k = e >> 5, l = e & 31;
        float4 v;
        if (k < DIM) {
            v.x = W[(4 * l + 0) * DIM + k];
            v.y = W[(4 * l + 1) * DIM + k];
            v.z = W[(4 * l + 2) * DIM + k];
            v.w = W[(4 * l + 3) * DIM + k];
        } else {
            v = make_float4(0.0f, 0.0f, 0.0f, 0.0f);
        }
        WTp[e] = v;
    }
    __syncthreads();
    if (row >= BATCH) return;             // last CTA's surplus warps exit

    const int dbase = 4 * lane;                            // this lane's dims

    const float4 bv = *(const float4*)(bias + dbase);
    float4 m = *(const float4*)(mem0 + (size_t)row * DIM + dbase);

    // Spike flags for dims 4l..4l+3; ballot word c: bit l = flag of dim 4l+c.
    float4 sv = *(const float4*)(sp0 + (size_t)row * DIM + dbase);
    bool f0 = sv.x != 0.0f, f1 = sv.y != 0.0f, f2 = sv.z != 0.0f, f3 = sv.w != 0.0f;
    unsigned w0 = __ballot_sync(0xffffffffu, f0);
    unsigned w1 = __ballot_sync(0xffffffffu, f1);
    unsigned w2 = __ballot_sync(0xffffffffu, f2);
    unsigned w3 = __ballot_sync(0xffffffffu, f3);

    const size_t step_stride = (size_t)BATCH * DIM;       // 131072
    const float* xp = x   + (size_t)row * DIM + dbase;
    float*       op = out + (size_t)row * DIM + dbase;

    float4 xa = *(const float4*)xp;                       // step-0 prefetch

    const unsigned mlt = (1u << lane) - 1u;               // lanemask_lt
    const char* Wlb = (const char*)(WTp + lane);          // +k*512 bytes per k
    unsigned* cb_base = cbuf + warp * 2 * CBUF_U32;

    for (int i = 0; i < NSTEP; i++) {
        // Register prefetch 1 ahead; L2 prefetch hint 2 ahead (no live regs).
        const float* xq = (i + 1 < NSTEP) ? (xp + step_stride) : xp;
        float4 xn = *(const float4*)xq;
        if (i + 2 < NSTEP) {
            asm volatile("prefetch.global.L2 [%0];"
                         :: "l"(xp + 2 * step_stride));
        }

        // ---- compaction: rank(4l+c) = S + sum_{c'<c} bit_l(w_c') ----
        unsigned* cb = cb_base + (i & 1) * CBUF_U32;
        unsigned S = __popc(w0 & mlt) + __popc(w1 & mlt)
                   + __popc(w2 & mlt) + __popc(w3 & mlt);
        unsigned b0 = (w0 >> lane) & 1u;
        unsigned b1 = (w1 >> lane) & 1u;
        unsigned b2 = (w2 >> lane) & 1u;
        unsigned r0 = S;
        unsigned r1 = S + b0;
        unsigned r2 = r1 + b1;
        unsigned r3 = r2 + b2;
        unsigned cnt = __popc(w0) + __popc(w1) + __popc(w2) + __popc(w3);

        if (lane < 4) cb[cnt + lane] = 128u;              // sentinels -> zeros
        if (f0) cb[r0] = (unsigned)(dbase + 0);
        if (f1) cb[r1] = (unsigned)(dbase + 1);
        if (f2) cb[r2] = (unsigned)(dbase + 2);
        if (f3) cb[r3] = (unsigned)(dbase + 3);
        __syncwarp();

        // ---- z[d] = ascending-k sparse sum; pads add exact +0.0 ----
        float z0 = 0.0f, z1 = 0.0f, z2 = 0.0f, z3 = 0.0f;
        const uint4* cb4 = (const uint4*)cb;
        for (unsigned j = 0; j < cnt; j += 4) {
            uint4 id = cb4[j >> 2];                       // broadcast LDS.128
            float4 a = *(const float4*)(Wlb + id.x * 512);
            float4 b = *(const float4*)(Wlb + id.y * 512);
            float4 c = *(const float4*)(Wlb + id.z * 512);
            float4 d = *(const float4*)(Wlb + id.w * 512);
            z0 = __fadd_rn(z0, a.x); z1 = __fadd_rn(z1, a.y);
            z2 = __fadd_rn(z2, a.z); z3 = __fadd_rn(z3, a.w);
            z0 = __fadd_rn(z0, b.x); z1 = __fadd_rn(z1, b.y);
            z2 = __fadd_rn(z2, b.z); z3 = __fadd_rn(z3, b.w);
            z0 = __fadd_rn(z0, c.x); z1 = __fadd_rn(z1, c.y);
            z2 = __fadd_rn(z2, c.z); z3 = __fadd_rn(z3, c.w);
            z0 = __fadd_rn(z0, d.x); z1 = __fadd_rn(z1, d.y);
            z2 = __fadd_rn(z2, d.z); z3 = __fadd_rn(z3, d.w);
        }

        // gamma = (1 + tanh(z + b)) * 0.5   (unfused, XLA rounding)
        float t0 = xla_tanh(__fadd_rn(z0, bv.x));
        float t1 = xla_tanh(__fadd_rn(z1, bv.y));
        float t2 = xla_tanh(__fadd_rn(z2, bv.z));
        float t3 = xla_tanh(__fadd_rn(z3, bv.w));
        float g0 = __fmul_rn(__fadd_rn(1.0f, t0), 0.5f);
        float g1 = __fmul_rn(__fadd_rn(1.0f, t1), 0.5f);
        float g2 = __fmul_rn(__fadd_rn(1.0f, t2), 0.5f);
        float g3 = __fmul_rn(__fadd_rn(1.0f, t3), 0.5f);

        // m = m + x * gamma  (mul then add, unfused)
        m.x = __fadd_rn(m.x, __fmul_rn(xa.x, g0));
        m.y = __fadd_rn(m.y, __fmul_rn(xa.y, g1));
        m.z = __fadd_rn(m.z, __fmul_rn(xa.z, g2));
        m.w = __fadd_rn(m.w, __fmul_rn(xa.w, g3));

        // spike = (m >= 1). Ballots FIRST (they feed next step's chain);
        // store + m-reset happen in the ballot shadow.
        f0 = (m.x >= 1.0f); f1 = (m.y >= 1.0f); f2 = (m.z >= 1.0f); f3 = (m.w >= 1.0f);

        w0 = __ballot_sync(0xffffffffu, f0);
        w1 = __ballot_sync(0xffffffffu, f1);
        w2 = __ballot_sync(0xffffffffu, f2);
        w3 = __ballot_sync(0xffffffffu, f3);

        float4 s;
        s.x = f0 ? 1.0f : 0.0f;  s.y = f1 ? 1.0f : 0.0f;
        s.z = f2 ? 1.0f : 0.0f;  s.w = f3 ? 1.0f : 0.0f;
        *(float4*)op = s;                                 // one STG.128

        m.x = f0 ? 0.0f : m.x;  m.y = f1 ? 0.0f : m.y;
        m.z = f2 ? 0.0f : m.z;  m.w = f3 ? 0.0f : m.w;

        xa = xn;
        xp += step_stride;
        op += step_stride;
    }
}

extern "C" void kernel_launch(void* const* d_in, const int* in_sizes, int n_in,
                              void* d_out, int out_size)
{
    (void)in_sizes; (void)n_in; (void)out_size;
    const float* x    = (const float*)d_in[0];
    const float* mem0 = (const float*)d_in[1];
    const float* sp0  = (const float*)d_in[2];
    const float* Wgs  = (const float*)d_in[3];
    const float* bgs  = (const float*)d_in[4];
    // d_in[5], d_in[6] (W_gt_w, W_gt_b) are dead in the reference's 3D branch.
    float* out = (float*)d_out;

    (void)cudaFuncSetAttribute(stc_lif_kernel,
                               cudaFuncAttributeMaxDynamicSharedMemorySize,
                               SMEM_BYTES);
    stc_lif_kernel<<<NCTAS, NTHREADS, SMEM_BYTES>>>(x, mem0, sp0, Wgs, bgs, out);
}

// round 14
// speedup vs baseline: 1.7790x; 1.0072x over previous
#include <cuda_runtime.h>
#include <cstdint>

// STC_LIF recurrence, exact-fp32 sparse formulation.
// R13/R14: (1) cp.async smem staging of x at depth 2 — registerless deep
// prefetch; each thread stages its own 16B for step i+2 into a 4-slot ring,
// wait_group 2 guarantees step i's data, read via LDS early in the step
// (off-chain). Removes the suspected partially-exposed DRAM latency of the
// 1-ahead register prefetch without R9's register-rotation pathology.
// (2) compaction (ranks+STS+syncwarp) moved to end-of-step, right after the
// ballots, so stores/loop overhead sit between STS and the next id-LDS.
// Gather/tanh/order byte-identical to the rel_err=0.0 R12 kernel.

#define NSTEP 512
#define BATCH 1024
#define DIM 128
#define ROWS_PER_CTA 7
#define NCTAS ((BATCH + ROWS_PER_CTA - 1) / ROWS_PER_CTA)   // 147
#define NTHREADS (ROWS_PER_CTA * 32)                         // 224
#define W_KENT 129                            // k = 0..127 real, k = 128 zeros
#define SMEM_W_BYTES (W_KENT * 32 * 16)       // 66048
#define CBUF_U32 132                          // cnt(<=128) + 4 sentinels
#define SMEM_CBUF_BYTES (ROWS_PER_CTA * 2 * CBUF_U32 * 4)    // 7392
#define SMEM_XBUF_BYTES (4 * NTHREADS * 16)                  // 14336
#define SMEM_BYTES (SMEM_W_BYTES + SMEM_CBUF_BYTES + SMEM_XBUF_BYTES)

// XLA / Eigen fast tanh for f32 (matches jnp.tanh lowering; verified exact).
__device__ __forceinline__ float xla_tanh(float x) {
    float cx = fmaxf(fminf(x, 7.90531110763549805f), -7.90531110763549805f);
    float x2 = __fmul_rn(cx, cx);
    float p = __fmaf_rn(x2, -2.76076847742355e-16f, 2.00018790482477e-13f);
    p = __fmaf_rn(x2, p, -8.60467152213735e-11f);
    p = __fmaf_rn(x2, p, 5.12229709037114e-08f);
    p = __fmaf_rn(x2, p, 1.48572235717979e-05f);
    p = __fmaf_rn(x2, p, 6.37261928875436e-04f);
    p = __fmaf_rn(x2, p, 4.89352455891786e-03f);
    p = __fmul_rn(cx, p);
    float q = __fmaf_rn(x2, 1.19825839466702e-06f, 1.18534705686654e-04f);
    q = __fmaf_rn(x2, q, 2.26843463243900e-03f);
    q = __fmaf_rn(x2, q, 4.89352518554385e-03f);
    float t = __fdiv_rn(p, q);
    return (fabsf(x) < 0.0004f) ? x : t;
}

__global__ void __launch_bounds__(NTHREADS, 1)
stc_lif_kernel(const float* __restrict__ x,
               const float* __restrict__ mem0,
               const float* __restrict__ sp0,
               const float* __restrict__ W,      // [D, D], z[d] = sum_k s[k]*W[d,k]
               const float* __restrict__ bias,   // [D]
               float* __restrict__ out)
{
    // WTp[k*32 + l] is a float4 = { W[4l+0][k], W[4l+1][k], W[4l+2][k],
    // W[4l+3][k] }; entry k=128 is zeros (sentinel for padded slots).
    extern __shared__ unsigned char smem_raw[];
    float4*   WTp  = (float4*)smem_raw;
    unsigned* cbuf = (unsigned*)(smem_raw + SMEM_W_BYTES);
    float4*   xbuf = (float4*)(smem_raw + SMEM_W_BYTES + SMEM_CBUF_BYTES);

    const int tid  = threadIdx.x;
    const int lane = tid & 31;
    const int warp = tid >> 5;
    const int row  = blockIdx.x * ROWS_PER_CTA + warp;    // 0..1023 (+tail)

    for (int e = tid; e < W_KENT * 32; e += NTHREADS) {
        int k = e >> 5, l = e & 31;
        float4 v;
        if (k < DIM) {
            v.x = W[(4 * l + 0) * DIM + k];
            v.y = W[(4 * l + 1) * DIM + k];
            v.z = W[(4 * l + 2) * DIM + k];
            v.w = W[(4 * l + 3) * DIM + k];
        } else {
            v = make_float4(0.0f, 0.0f, 0.0f, 0.0f);
        }
        WTp[e] = v;
    }
    __syncthreads();
    if (row >= BATCH) return;             // last CTA's surplus warps exit

    const int dbase = 4 * lane;                            // this lane's dims

    const float4 bv = *(const float4*)(bias + dbase);
    float4 m = *(const float4*)(mem0 + (size_t)row * DIM + dbase);

    // Spike flags for dims 4l..4l+3; ballot word c: bit l = flag of dim 4l+c.
    float4 sv = *(const float4*)(sp0 + (size_t)row * DIM + dbase);
    bool f0 = sv.x != 0.0f, f1 = sv.y != 0.0f, f2 = sv.z != 0.0f, f3 = sv.w != 0.0f;
    unsigned w0 = __ballot_sync(0xffffffffu, f0);
    unsigned w1 = __ballot_sync(0xffffffffu, f1);
    unsigned w2 = __ballot_sync(0xffffffffu, f2);
    unsigned w3 = __ballot_sync(0xffffffffu, f3);

    const size_t step_stride = (size_t)BATCH * DIM;       // 131072
    const float* xp = x   + (size_t)row * DIM + dbase;    // x for step i
    float*       op = out + (size_t)row * DIM + dbase;

    const unsigned mlt = (1u << lane) - 1u;               // lanemask_lt
    const char* Wlb = (const char*)(WTp + lane);          // +k*512 bytes per k
    unsigned* cb_base = cbuf + warp * 2 * CBUF_U32;

    // x staging ring: slot s holds this thread's 16B of x for step with
    // (step & 3) == s.
    float4* my_x = xbuf + tid;                            // +NTHREADS per slot
    unsigned xs_base = (unsigned)__cvta_generic_to_shared(my_x);

    // Prologue: stage x for steps 0 and 1 (two committed groups).
    asm volatile("cp.async.ca.shared.global [%0], [%1], 16;\n"
                 "cp.async.commit_group;"
                 :: "r"(xs_base), "l"(xp) : "memory");
    asm volatile("cp.async.ca.shared.global [%0], [%1], 16;\n"
                 "cp.async.commit_group;"
                 :: "r"(xs_base + NTHREADS * 16), "l"(xp + step_stride)
                 : "memory");

    // Prologue compaction for step 0 into cbuf slot 0.
    unsigned cnt;
    {
        unsigned* cb = cb_base;
        unsigned S = __popc(w0 & mlt) + __popc(w1 & mlt)
                   + __popc(w2 & mlt) + __popc(w3 & mlt);
        unsigned bb0 = (w0 >> lane) & 1u;
        unsigned bb1 = (w1 >> lane) & 1u;
        unsigned bb2 = (w2 >> lane) & 1u;
        unsigned r0 = S, r1 = S + bb0, r2 = r1 + bb1, r3 = r2 + bb2;
        cnt = __popc(w0) + __popc(w1) + __popc(w2) + __popc(w3);
        if (lane < 4) cb[cnt + lane] = 128u;
        if (f0) cb[r0] = (unsigned)(dbase + 0);
        if (f1) cb[r1] = (unsigned)(dbase + 1);
        if (f2) cb[r2] = (unsigned)(dbase + 2);
        if (f3) cb[r3] = (unsigned)(dbase + 3);
        __syncwarp();
    }

    for (int i = 0; i < NSTEP; i++) {
        // Stage x for step i+2 (skip near end but always commit to keep
        // group counts aligned); then guarantee step i's data and read it.
        if (i + 2 < NSTEP) {
            unsigned dst = xs_base + ((unsigned)((i + 2) & 3)) * (NTHREADS * 16);
            const float* src = xp + 2 * step_stride;
            asm volatile("cp.async.ca.shared.global [%0], [%1], 16;"
                         :: "r"(dst), "l"(src) : "memory");
        }
        asm volatile("cp.async.commit_group;" ::: "memory");
        asm volatile("cp.async.wait_group 2;" ::: "memory");
        float4 xa = my_x[(i & 3) * NTHREADS];             // LDS.128, off-chain

        // ---- z[d] = ascending-k sparse sum; pads add exact +0.0 ----
        float z0 = 0.0f, z1 = 0.0f, z2 = 0.0f, z3 = 0.0f;
        const uint4* cb4 = (const uint4*)(cb_base + (i & 1) * CBUF_U32);
        for (unsigned j = 0; j < cnt; j += 4) {
            uint4 id = cb4[j >> 2];                       // broadcast LDS.128
            float4 a = *(const float4*)(Wlb + id.x * 512);
            float4 b = *(const float4*)(Wlb + id.y * 512);
            float4 c = *(const float4*)(Wlb + id.z * 512);
            float4 d = *(const float4*)(Wlb + id.w * 512);
            z0 = __fadd_rn(z0, a.x); z1 = __fadd_rn(z1, a.y);
            z2 = __fadd_rn(z2, a.z); z3 = __fadd_rn(z3, a.w);
            z0 = __fadd_rn(z0, b.x); z1 = __fadd_rn(z1, b.y);
            z2 = __fadd_rn(z2, b.z); z3 = __fadd_rn(z3, b.w);
            z0 = __fadd_rn(z0, c.x); z1 = __fadd_rn(z1, c.y);
            z2 = __fadd_rn(z2, c.z); z3 = __fadd_rn(z3, c.w);
            z0 = __fadd_rn(z0, d.x); z1 = __fadd_rn(z1, d.y);
            z2 = __fadd_rn(z2, d.z); z3 = __fadd_rn(z3, d.w);
        }

        // gamma = (1 + tanh(z + b)) * 0.5   (unfused, XLA rounding)
        float t0 = xla_tanh(__fadd_rn(z0, bv.x));
        float t1 = xla_tanh(__fadd_rn(z1, bv.y));
        float t2 = xla_tanh(__fadd_rn(z2, bv.z));
        float t3 = xla_tanh(__fadd_rn(z3, bv.w));
        float g0 = __fmul_rn(__fadd_rn(1.0f, t0), 0.5f);
        float g1 = __fmul_rn(__fadd_rn(1.0f, t1), 0.5f);
        float g2 = __fmul_rn(__fadd_rn(1.0f, t2), 0.5f);
        float g3 = __fmul_rn(__fadd_rn(1.0f, t3), 0.5f);

        // m = m + x * gamma  (mul then add, unfused)
        m.x = __fadd_rn(m.x, __fmul_rn(xa.x, g0));
        m.y = __fadd_rn(m.y, __fmul_rn(xa.y, g1));
        m.z = __fadd_rn(m.z, __fmul_rn(xa.z, g2));
        m.w = __fadd_rn(m.w, __fmul_rn(xa.w, g3));

        // spike = (m >= 1). Ballots first, then compaction for step i+1;
        // out-store and m-reset drop into the shadow.
        f0 = (m.x >= 1.0f); f1 = (m.y >= 1.0f); f2 = (m.z >= 1.0f); f3 = (m.w >= 1.0f);

        w0 = __ballot_sync(0xffffffffu, f0);
        w1 = __ballot_sync(0xffffffffu, f1);
        w2 = __ballot_sync(0xffffffffu, f2);
        w3 = __ballot_sync(0xffffffffu, f3);

        // ---- compaction for step i+1 into cbuf slot ((i+1)&1) ----
        {
            unsigned* cb = cb_base + ((i + 1) & 1) * CBUF_U32;
            unsigned S = __popc(w0 & mlt) + __popc(w1 & mlt)
                       + __popc(w2 & mlt) + __popc(w3 & mlt);
            unsigned bb0 = (w0 >> lane) & 1u;
            unsigned bb1 = (w1 >> lane) & 1u;
            unsigned bb2 = (w2 >> lane) & 1u;
            unsigned r0 = S, r1 = S + bb0, r2 = r1 + bb1, r3 = r2 + bb2;
            cnt = __popc(w0) + __popc(w1) + __popc(w2) + __popc(w3);
            if (lane < 4) cb[cnt + lane] = 128u;
            if (f0) cb[r0] = (unsigned)(dbase + 0);
            if (f1) cb[r1] = (unsigned)(dbase + 1);
            if (f2) cb[r2] = (unsigned)(dbase + 2);
            if (f3) cb[r3] = (unsigned)(dbase + 3);
        }

        float4 s;
        s.x = f0 ? 1.0f : 0.0f;  s.y = f1 ? 1.0f : 0.0f;
        s.z = f2 ? 1.0f : 0.0f;  s.w = f3 ? 1.0f : 0.0f;
        *(float4*)op = s;                                 // one STG.128

        m.x = f0 ? 0.0f : m.x;  m.y = f1 ? 0.0f : m.y;
        m.z = f2 ? 0.0f : m.z;  m.w = f3 ? 0.0f : m.w;

        __syncwarp();                                     // publish compaction

        xp += step_stride;
        op += step_stride;
    }
}

extern "C" void kernel_launch(void* const* d_in, const int* in_sizes, int n_in,
                              void* d_out, int out_size)
{
    (void)in_sizes; (void)n_in; (void)out_size;
    const float* x    = (const float*)d_in[0];
    const float* mem0 = (const float*)d_in[1];
    const float* sp0  = (const float*)d_in[2];
    const float* Wgs  = (const float*)d_in[3];
    const float* bgs  = (const float*)d_in[4];
    // d_in[5], d_in[6] (W_gt_w, W_gt_b) are dead in the reference's 3D branch.
    float* out = (float*)d_out;

    (void)cudaFuncSetAttribute(stc_lif_kernel,
                               cudaFuncAttributeMaxDynamicSharedMemorySize,
                               SMEM_BYTES);
    stc_lif_kernel<<<NCTAS, NTHREADS, SMEM_BYTES>>>(x, mem0, sp0, Wgs, bgs, out);
}